// round 1
// baseline (speedup 1.0000x reference)
#include <cuda_runtime.h>
#include <cstddef>

// MultiDecoder: A=10 independent MLPs 12 -> 128 -> 256 -> 200 over 32768 tokens.
// Fused single kernel: block = (64-token tile, articulator).
// Phase A: h1 = relu(x_g @ W1 + b1)     (tiny)
// Phase B: h2 = relu(h1 @ W2 + b2)      (64x256x128 GEMM, reg-tiled 4x16)
// Phase C: out = h2 @ W3 + b3           (64x208x256 GEMM, reg-tiled 4x13, cols padded)
// Intermediates kept transposed [k][token] in smem for float4 A-loads.
// Output staged through smem for coalesced global stores.

#define NA   10
#define NC   12
#define NH2  128
#define NH   256
#define NF   200
#define NFP  208      // padded col count for phase C (16 groups x 13)
#define NL   120
#define NTOK 32768
#define TM   64       // tokens per block
#define NTHREADS 256
#define KT   32       // k-chunk staged in smem

// dynamic smem layout (floats):
//   s_h1 [NH2][TM]   = 8192      offset 0
//   s_h2 [NH][TM]    = 16384     offset 8192   (reused as s_out[TM][NF]=12800)
//   s_w  [KT][NH]    = 8192      offset 24576  (phase C uses [KT][NFP]=6656)
//   s_x  [TM][NC]    = 768       offset 32768
#define SMEM_FLOATS (NH2*TM + NH*TM + KT*NH + TM*NC)
#define SMEM_BYTES  (SMEM_FLOATS * (int)sizeof(float))

__global__ void __launch_bounds__(NTHREADS, 1)
multidecoder_kernel(const float* __restrict__ x,
                    const float* __restrict__ W1, const float* __restrict__ b1,
                    const float* __restrict__ W2, const float* __restrict__ b2,
                    const float* __restrict__ W3, const float* __restrict__ b3,
                    const int*   __restrict__ idx,
                    float* __restrict__ out)
{
    extern __shared__ float smem[];
    float* s_h1 = smem;                      // [NH2][TM]
    float* s_h2 = smem + NH2 * TM;           // [NH][TM]
    float* s_w  = smem + NH2 * TM + NH * TM; // [KT][NH] / [KT][NFP]
    float* s_x  = s_w + KT * NH;             // [TM][NC]

    const int a   = blockIdx.y;
    const int n0  = blockIdx.x * TM;
    const int tid = threadIdx.x;

    // ---------------- load gathered x tile ----------------
    for (int i = tid; i < TM * NC; i += NTHREADS) {
        int t = i / NC, c = i % NC;
        s_x[i] = x[(size_t)(n0 + t) * NL + idx[a * NC + c]];
    }
    __syncthreads();

    // ---------------- phase A: layer 1 (12 -> 128) ----------------
    {
        const float* W1a = W1 + a * NC * NH2;
        const float* b1a = b1 + a * NH2;
        const int t  = tid & (TM - 1);
        const int hg = tid >> 6;             // 0..3, 32 h-values each
        float xv[NC];
        #pragma unroll
        for (int c = 0; c < NC; c++) xv[c] = s_x[t * NC + c];
        #pragma unroll 4
        for (int j = 0; j < 32; j++) {
            const int h = hg * 32 + j;
            float acc = b1a[h];
            #pragma unroll
            for (int c = 0; c < NC; c++)
                acc = fmaf(xv[c], W1a[c * NH2 + h], acc);
            s_h1[h * TM + t] = fmaxf(acc, 0.0f);
        }
    }
    __syncthreads();

    // ---------------- phase B: layer 2 (128 -> 256) ----------------
    {
        const float* W2a = W2 + (size_t)a * NH2 * NH;
        const int tx = tid & 15;   // tokens 4*tx .. 4*tx+3
        const int ty = tid >> 4;   // cols  16*ty .. 16*ty+15
        float acc[4][16];
        #pragma unroll
        for (int tt = 0; tt < 4; tt++)
            #pragma unroll
            for (int jj = 0; jj < 16; jj++) acc[tt][jj] = 0.0f;

        for (int kc = 0; kc < NH2; kc += KT) {
            __syncthreads();  // previous s_w chunk fully consumed
            // stage W2[kc..kc+KT) rows, vectorized
            const float4* src = (const float4*)(W2a + (size_t)kc * NH);
            float4* dst = (float4*)s_w;
            for (int i = tid; i < KT * NH / 4; i += NTHREADS) dst[i] = src[i];
            __syncthreads();

            #pragma unroll 4
            for (int kk = 0; kk < KT; kk++) {
                float4 av = *(const float4*)(s_h1 + (kc + kk) * TM + 4 * tx);
                float ar[4] = {av.x, av.y, av.z, av.w};
                float br[16];
                #pragma unroll
                for (int m = 0; m < 4; m++) {
                    float4 bv = *(const float4*)(s_w + kk * NH + 16 * ty + 4 * m);
                    br[4 * m + 0] = bv.x; br[4 * m + 1] = bv.y;
                    br[4 * m + 2] = bv.z; br[4 * m + 3] = bv.w;
                }
                #pragma unroll
                for (int tt = 0; tt < 4; tt++)
                    #pragma unroll
                    for (int jj = 0; jj < 16; jj++)
                        acc[tt][jj] = fmaf(ar[tt], br[jj], acc[tt][jj]);
            }
        }
        __syncthreads();  // all reads of s_h1/s_w done before s_h2 write races next staging
        const float* b2a = b2 + a * NH;
        #pragma unroll
        for (int jj = 0; jj < 16; jj++) {
            const int j = 16 * ty + jj;
            const float bb = b2a[j];
            #pragma unroll
            for (int tt = 0; tt < 4; tt++)
                s_h2[j * TM + 4 * tx + tt] = fmaxf(acc[tt][jj] + bb, 0.0f);
        }
    }

    // ---------------- phase C: layer 3 (256 -> 200) ----------------
    {
        const float* W3a = W3 + (size_t)a * NH * NF;
        const int tx = tid & 15;   // tokens 4*tx .. 4*tx+3
        const int ty = tid >> 4;   // cols  13*ty .. 13*ty+12 (padded to 208)
        float acc[4][13];
        #pragma unroll
        for (int tt = 0; tt < 4; tt++)
            #pragma unroll
            for (int m = 0; m < 13; m++) acc[tt][m] = 0.0f;

        for (int kc = 0; kc < NH; kc += KT) {
            __syncthreads();  // also covers: s_h2 writes visible before first read
            // stage W3 chunk [KT][NFP], zero-padded cols >= NF
            for (int i = tid; i < KT * NFP; i += NTHREADS) {
                int kk = i / NFP, j = i % NFP;
                s_w[i] = (j < NF) ? W3a[(size_t)(kc + kk) * NF + j] : 0.0f;
            }
            __syncthreads();

            #pragma unroll 4
            for (int kk = 0; kk < KT; kk++) {
                float4 av = *(const float4*)(s_h2 + (kc + kk) * TM + 4 * tx);
                float ar[4] = {av.x, av.y, av.z, av.w};
                float br[13];
                #pragma unroll
                for (int m = 0; m < 13; m++) br[m] = s_w[kk * NFP + 13 * ty + m];
                #pragma unroll
                for (int tt = 0; tt < 4; tt++)
                    #pragma unroll
                    for (int m = 0; m < 13; m++)
                        acc[tt][m] = fmaf(ar[tt], br[m], acc[tt][m]);
            }
        }
        __syncthreads();               // all s_h2 reads done; reuse it as s_out
        float* s_out = s_h2;           // [TM][NF]
        const float* b3a = b3 + a * NF;
        #pragma unroll
        for (int m = 0; m < 13; m++) {
            const int j = 13 * ty + m;
            if (j < NF) {
                const float bb = b3a[j];
                #pragma unroll
                for (int tt = 0; tt < 4; tt++)
                    s_out[(4 * tx + tt) * NF + j] = acc[tt][m] + bb;
            }
        }
        __syncthreads();
        // coalesced global store: 64 tokens x 200 floats
        for (int i = tid; i < TM * NF; i += NTHREADS) {
            int t = i / NF, j = i % NF;
            out[((size_t)(n0 + t) * NA + a) * NF + j] = s_out[i];
        }
    }
}

extern "C" void kernel_launch(void* const* d_in, const int* in_sizes, int n_in,
                              void* d_out, int out_size)
{
    // Identify inputs by element count (all distinct) — robust to ordering.
    const float *x = nullptr, *W1 = nullptr, *b1 = nullptr, *W2 = nullptr,
                *b2 = nullptr, *W3 = nullptr, *b3 = nullptr;
    const int* idx = nullptr;
    for (int i = 0; i < n_in; i++) {
        switch (in_sizes[i]) {
            case NTOK * NL:       x   = (const float*)d_in[i]; break;   // 3932160
            case NA * NC * NH2:   W1  = (const float*)d_in[i]; break;   // 15360
            case NA * NH2:        b1  = (const float*)d_in[i]; break;   // 1280
            case NA * NH2 * NH:   W2  = (const float*)d_in[i]; break;   // 327680
            case NA * NH:         b2  = (const float*)d_in[i]; break;   // 2560
            case NA * NH * NF:    W3  = (const float*)d_in[i]; break;   // 512000
            case NA * NF:         b3  = (const float*)d_in[i]; break;   // 2000
            case NA * NC:         idx = (const int*)d_in[i];   break;   // 120
            default: break;
        }
    }

    cudaFuncSetAttribute(multidecoder_kernel,
                         cudaFuncAttributeMaxDynamicSharedMemorySize, SMEM_BYTES);

    dim3 grid(NTOK / TM, NA);
    multidecoder_kernel<<<grid, NTHREADS, SMEM_BYTES>>>(
        x, W1, b1, W2, b2, W3, b3, idx, (float*)d_out);
}